// round 11
// baseline (speedup 1.0000x reference)
#include <cuda_runtime.h>
#include <cuda_bf16.h>
#include <cstdint>

#define BATCH 4
#define SEQ   1370
#define NH    16
#define HD    64
#define HID   1024
#define NTOK  (BATCH * SEQ)   // 5480

// Scratch: projected Q/K/V in [B, NH, L, HD] layout.
__device__ float g_q[(size_t)BATCH * NH * SEQ * HD];
__device__ float g_k[(size_t)BATCH * NH * SEQ * HD];
__device__ float g_v[(size_t)BATCH * NH * SEQ * HD];

// ===========================================================================
// Helpers
// ===========================================================================
__device__ __forceinline__ uint32_t smem_u32(const void* p) {
    uint32_t a;
    asm("{ .reg .u64 t; cvta.to.shared.u64 t, %1; cvt.u32.u64 %0, t; }"
        : "=r"(a) : "l"(p));
    return a;
}

#define LDMX4(r, addr) \
    asm volatile("ldmatrix.sync.aligned.m8n8.x4.shared.b16 {%0,%1,%2,%3}, [%4];" \
        : "=r"((r)[0]), "=r"((r)[1]), "=r"((r)[2]), "=r"((r)[3]) : "r"(addr))

#define LDMX4T(r, addr) \
    asm volatile("ldmatrix.sync.aligned.m8n8.x4.trans.shared.b16 {%0,%1,%2,%3}, [%4];" \
        : "=r"((r)[0]), "=r"((r)[1]), "=r"((r)[2]), "=r"((r)[3]) : "r"(addr))

#define MMA16816(d, a, b0, b1) \
    asm volatile("mma.sync.aligned.m16n8k16.row.col.f32.bf16.bf16.f32 " \
        "{%0,%1,%2,%3}, {%4,%5,%6,%7}, {%8,%9}, {%0,%1,%2,%3};" \
        : "+f"((d)[0]), "+f"((d)[1]), "+f"((d)[2]), "+f"((d)[3]) \
        : "r"((a)[0]), "r"((a)[1]), "r"((a)[2]), "r"((a)[3]), "r"(b0), "r"(b1))

__device__ __forceinline__ uint32_t pack_bf16(float lo, float hi) {
    uint32_t r;
    asm("cvt.rn.bf16x2.f32 %0, %1, %2;" : "=r"(r) : "f"(hi), "f"(lo));
    return r;
}

// fp32x4 -> bf16 hi/lo planes, 8B each, to smem.
__device__ __forceinline__ void split_sts(char* hp, char* lp, uint32_t off, float4 v) {
    __nv_bfloat16 h0 = __float2bfloat16_rn(v.x);
    __nv_bfloat16 h1 = __float2bfloat16_rn(v.y);
    __nv_bfloat16 h2 = __float2bfloat16_rn(v.z);
    __nv_bfloat16 h3 = __float2bfloat16_rn(v.w);
    float l0 = v.x - __bfloat162float(h0);
    float l1 = v.y - __bfloat162float(h1);
    float l2 = v.z - __bfloat162float(h2);
    float l3 = v.w - __bfloat162float(h3);
    __nv_bfloat162 hA = __halves2bfloat162(h0, h1);
    __nv_bfloat162 hB = __halves2bfloat162(h2, h3);
    uint32_t lA = pack_bf16(l0, l1);
    uint32_t lB = pack_bf16(l2, l3);
    *(uint2*)(hp + off) = make_uint2(*(uint32_t*)&hA, *(uint32_t*)&hB);
    *(uint2*)(lp + off) = make_uint2(lA, lB);
}

// ===========================================================================
// Phase 1: QKV projection on mma.sync (R8 variant — measured best at ~357us).
// Block tile 128x128, 8 warps (4m x 2n), BK=32, double-buffered smem.
// Y = Xh*Wh + Xh*Wl + Xl*Wh  (fp32 accum; ll dropped, error ~2^-18)
// ===========================================================================
#define QBK     32
#define QROWB   80
#define QTILE   (128 * QROWB)
#define QBUF    (4 * QTILE)
#define QK_SMEM (2 * QBUF)           // 81920
#define QCHUNKS (HID / QBK)

__global__ __launch_bounds__(256)
void qkv_mma(const float* __restrict__ X,
             const float* __restrict__ Wq, const float* __restrict__ bq,
             const float* __restrict__ Wk, const float* __restrict__ bk,
             const float* __restrict__ Wv, const float* __restrict__ bv)
{
    extern __shared__ char sm[];
    const uint32_t sbase = smem_u32(sm);

    const int tid  = threadIdx.x;
    const int lane = tid & 31;
    const int wid  = tid >> 5;
    const int wm   = wid & 3;
    const int wn   = wid >> 2;

    const int m0   = blockIdx.x * 128;
    const int nb   = blockIdx.y;
    const int proj = nb >> 3;
    const int o0   = (nb & 7) * 128;

    const float* W    = (proj == 0) ? Wq : (proj == 1) ? Wk : Wv;
    const float* bias = (proj == 0) ? bq : (proj == 1) ? bk : bv;
    float*       dst  = (proj == 0) ? g_q : (proj == 1) ? g_k : g_v;

    float acc[2][8][4];
    #pragma unroll
    for (int mt = 0; mt < 2; mt++)
        #pragma unroll
        for (int nt = 0; nt < 8; nt++)
            #pragma unroll
            for (int r = 0; r < 4; r++) acc[mt][nt][r] = 0.f;

    float4 stA[4], stB[4];
    const int ldRow = tid >> 3;
    const int ldC   = (tid & 7) << 2;

    const uint32_t lmA = (uint32_t)((wm * 32 + (lane & 15)) * QROWB + (lane >> 4) * 16);
    const uint32_t lmB = (uint32_t)((wn * 64 + (lane & 15)) * QROWB + (lane >> 4) * 16);

    #pragma unroll
    for (int i = 0; i < 4; i++) {
        int row = ldRow + i * 32;
        int gm  = m0 + row;
        stA[i] = (gm < NTOK) ? *(const float4*)(X + (size_t)gm * HID + ldC)
                             : make_float4(0.f, 0.f, 0.f, 0.f);
        stB[i] = *(const float4*)(W + (size_t)(o0 + row) * HID + ldC);
    }
    {
        char* Ah = sm;            char* Al = sm + QTILE;
        char* Bh = sm + 2*QTILE;  char* Bl = sm + 3*QTILE;
        #pragma unroll
        for (int i = 0; i < 4; i++) {
            uint32_t off = (uint32_t)((ldRow + i * 32) * QROWB + ldC * 2);
            split_sts(Ah, Al, off, stA[i]);
            split_sts(Bh, Bl, off, stB[i]);
        }
    }
    __syncthreads();

    for (int c = 0; c < QCHUNKS; c++) {
        if (c + 1 < QCHUNKS) {
            int kc = (c + 1) * QBK;
            #pragma unroll
            for (int i = 0; i < 4; i++) {
                int row = ldRow + i * 32;
                int gm  = m0 + row;
                stA[i] = (gm < NTOK) ? *(const float4*)(X + (size_t)gm * HID + kc + ldC)
                                     : make_float4(0.f, 0.f, 0.f, 0.f);
                stB[i] = *(const float4*)(W + (size_t)(o0 + row) * HID + kc + ldC);
            }
        }

        const uint32_t Ahb = sbase + (c & 1) * QBUF;
        const uint32_t Alb = Ahb + QTILE;
        const uint32_t Bhb = Ahb + 2 * QTILE;
        const uint32_t Blb = Ahb + 3 * QTILE;

        #pragma unroll
        for (int kk = 0; kk < 2; kk++) {
            const uint32_t kb = kk * 32;
            uint32_t fAh[2][4], fAl[2][4], fB[4][4];
            #pragma unroll
            for (int mt = 0; mt < 2; mt++) {
                LDMX4(fAh[mt], Ahb + lmA + mt * (16 * QROWB) + kb);
                LDMX4(fAl[mt], Alb + lmA + mt * (16 * QROWB) + kb);
            }
            #pragma unroll
            for (int n2 = 0; n2 < 4; n2++)
                LDMX4(fB[n2], Bhb + lmB + n2 * (16 * QROWB) + kb);
            #pragma unroll
            for (int mt = 0; mt < 2; mt++)
                #pragma unroll
                for (int nt = 0; nt < 8; nt++)
                    MMA16816(acc[mt][nt], fAh[mt], fB[nt >> 1][nt & 1], fB[nt >> 1][2 + (nt & 1)]);
            #pragma unroll
            for (int mt = 0; mt < 2; mt++)
                #pragma unroll
                for (int nt = 0; nt < 8; nt++)
                    MMA16816(acc[mt][nt], fAl[mt], fB[nt >> 1][nt & 1], fB[nt >> 1][2 + (nt & 1)]);
            #pragma unroll
            for (int n2 = 0; n2 < 4; n2++)
                LDMX4(fB[n2], Blb + lmB + n2 * (16 * QROWB) + kb);
            #pragma unroll
            for (int mt = 0; mt < 2; mt++)
                #pragma unroll
                for (int nt = 0; nt < 8; nt++)
                    MMA16816(acc[mt][nt], fAh[mt], fB[nt >> 1][nt & 1], fB[nt >> 1][2 + (nt & 1)]);
        }

        if (c + 1 < QCHUNKS) {
            char* Ah = sm + ((c + 1) & 1) * QBUF;
            char* Al = Ah + QTILE;
            char* Bh = Ah + 2 * QTILE;
            char* Bl = Ah + 3 * QTILE;
            #pragma unroll
            for (int i = 0; i < 4; i++) {
                uint32_t off = (uint32_t)((ldRow + i * 32) * QROWB + ldC * 2);
                split_sts(Ah, Al, off, stA[i]);
                split_sts(Bh, Bl, off, stB[i]);
            }
        }
        __syncthreads();
    }

    const int g   = lane >> 2;
    const int tig = lane & 3;
    const int headBase = (o0 + wn * 64) >> 6;
    #pragma unroll
    for (int mt = 0; mt < 2; mt++) {
        #pragma unroll
        for (int half = 0; half < 2; half++) {
            int gm = m0 + wm * 32 + mt * 16 + g + half * 8;
            if (gm >= NTOK) continue;
            int bb = gm / SEQ;
            int ll = gm - bb * SEQ;
            float* dp = dst + (((size_t)bb * NH + headBase) * SEQ + ll) * HD;
            #pragma unroll
            for (int nt = 0; nt < 8; nt++) {
                int dd = nt * 8 + tig * 2;
                float2 bv = *(const float2*)(bias + o0 + wn * 64 + dd);
                float2 ov;
                ov.x = acc[mt][nt][half * 2 + 0] + bv.x;
                ov.y = acc[mt][nt][half * 2 + 1] + bv.y;
                *(float2*)(dp + dd) = ov;
            }
        }
    }
}

// ===========================================================================
// Phase 2: flash attention on mma.sync, restructured:
//  - CTA = 128 threads / 4 warps / 64 q rows (smem 55296 -> 4 CTAs/SM)
//  - MMA term-sweeps: each of the 3 compensation terms sweeps all 8
//    accumulators before revisiting one (RAW distance 8 MMAs > HMMA latency)
// ===========================================================================
#define FROWB 144
#define FA_QH 0
#define FA_QL (64 * FROWB)
#define FA_KH (2 * 64 * FROWB)
#define FA_KL (3 * 64 * FROWB)
#define FA_VH (4 * 64 * FROWB)
#define FA_VL (5 * 64 * FROWB)
#define FA_SMEM (6 * 64 * FROWB)     // 55296

__global__ __launch_bounds__(128, 4)
void flash_mma(float* __restrict__ out)
{
    extern __shared__ char sm[];
    const uint32_t sb = smem_u32(sm);

    const int tid  = threadIdx.x;
    const int lane = tid & 31;
    const int w    = tid >> 5;           // 0..3

    const int qt    = blockIdx.x;        // 0..21
    const int bh    = blockIdx.y;        // 0..63
    const int batch = bh >> 4;
    const int head  = bh & 15;
    const float* Q = g_q + (size_t)bh * SEQ * HD;
    const float* K = g_k + (size_t)bh * SEQ * HD;
    const float* V = g_v + (size_t)bh * SEQ * HD;
    const int q0 = qt * 64;

    // Load Q tile (64 rows), pre-scaled by 1/sqrt(64)=0.125 before split.
    #pragma unroll
    for (int i = 0; i < 8; i++) {
        int f   = i * 128 + tid;
        int row = f >> 4;
        int c4  = (f & 15) << 2;
        int gq  = q0 + row;
        float4 v = (gq < SEQ)
            ? *(const float4*)(Q + (size_t)gq * HD + c4)
            : make_float4(0.f, 0.f, 0.f, 0.f);
        v.x *= 0.125f; v.y *= 0.125f; v.z *= 0.125f; v.w *= 0.125f;
        split_sts(sm + FA_QH, sm + FA_QL, (uint32_t)(row * FROWB + c4 * 2), v);
    }

    const uint32_t lmQ  = (uint32_t)((w * 16 + (lane & 15)) * FROWB + (lane >> 4) * 16);
    const uint32_t lmKV = (uint32_t)((lane & 15) * FROWB + (lane >> 4) * 16);
    const int g   = lane >> 2;
    const int tig = lane & 3;

    float m0v = -1e30f, m1v = -1e30f, l0v = 0.f, l1v = 0.f;
    float O[8][4];
    #pragma unroll
    for (int nt = 0; nt < 8; nt++)
        #pragma unroll
        for (int r = 0; r < 4; r++) O[nt][r] = 0.f;

    for (int kv0 = 0; kv0 < SEQ; kv0 += 64) {
        __syncthreads();   // prior tile's ldmatrix done (and Q stores, iter 0)

        // Load K, V tiles (64 x 64 fp32 each), split to bf16 hi/lo.
        #pragma unroll
        for (int i = 0; i < 8; i++) {
            int f   = i * 128 + tid;
            int row = f >> 4;
            int c4  = (f & 15) << 2;
            int gk  = kv0 + row;
            float4 vk, vv;
            if (gk < SEQ) {
                vk = *(const float4*)(K + (size_t)gk * HD + c4);
                vv = *(const float4*)(V + (size_t)gk * HD + c4);
            } else {
                vk = make_float4(0.f, 0.f, 0.f, 0.f);
                vv = vk;
            }
            uint32_t off = (uint32_t)(row * FROWB + c4 * 2);
            split_sts(sm + FA_KH, sm + FA_KL, off, vk);
            split_sts(sm + FA_VH, sm + FA_VL, off, vv);
        }
        __syncthreads();

        // ---- S = Q @ K^T : per-term sweeps over all 8 accumulators ----
        float S[8][4];
        #pragma unroll
        for (int nt = 0; nt < 8; nt++)
            #pragma unroll
            for (int r = 0; r < 4; r++) S[nt][r] = 0.f;

        #pragma unroll
        for (int ks = 0; ks < 4; ks++) {
            uint32_t qh[4], ql[4], kh[4][4], kl[4][4];
            LDMX4(qh, sb + FA_QH + lmQ + ks * 32);
            LDMX4(ql, sb + FA_QL + lmQ + ks * 32);
            #pragma unroll
            for (int n16 = 0; n16 < 4; n16++) {
                LDMX4(kh[n16], sb + FA_KH + lmKV + n16 * (16 * FROWB) + ks * 32);
                LDMX4(kl[n16], sb + FA_KL + lmKV + n16 * (16 * FROWB) + ks * 32);
            }
            #pragma unroll
            for (int n16 = 0; n16 < 4; n16++) {          // hi * hi
                MMA16816(S[2*n16],   qh, kh[n16][0], kh[n16][2]);
                MMA16816(S[2*n16+1], qh, kh[n16][1], kh[n16][3]);
            }
            #pragma unroll
            for (int n16 = 0; n16 < 4; n16++) {          // hi * lo
                MMA16816(S[2*n16],   qh, kl[n16][0], kl[n16][2]);
                MMA16816(S[2*n16+1], qh, kl[n16][1], kl[n16][3]);
            }
            #pragma unroll
            for (int n16 = 0; n16 < 4; n16++) {          // lo * hi
                MMA16816(S[2*n16],   ql, kh[n16][0], kh[n16][2]);
                MMA16816(S[2*n16+1], ql, kh[n16][1], kh[n16][3]);
            }
        }

        // ---- key mask (last tile only) ----
        if (kv0 + 64 > SEQ) {
            #pragma unroll
            for (int nt = 0; nt < 8; nt++)
                #pragma unroll
                for (int e = 0; e < 4; e++)
                    if (kv0 + nt * 8 + tig * 2 + (e & 1) >= SEQ) S[nt][e] = -1e30f;
        }

        // ---- online softmax (rows g / g+8; reduce across quad lanes) ----
        float mx0 = -1e30f, mx1 = -1e30f;
        #pragma unroll
        for (int nt = 0; nt < 8; nt++) {
            mx0 = fmaxf(mx0, fmaxf(S[nt][0], S[nt][1]));
            mx1 = fmaxf(mx1, fmaxf(S[nt][2], S[nt][3]));
        }
        #pragma unroll
        for (int off = 1; off <= 2; off <<= 1) {
            mx0 = fmaxf(mx0, __shfl_xor_sync(0xffffffffu, mx0, off));
            mx1 = fmaxf(mx1, __shfl_xor_sync(0xffffffffu, mx1, off));
        }
        float mnew0 = fmaxf(m0v, mx0);
        float mnew1 = fmaxf(m1v, mx1);
        float a0 = __expf(m0v - mnew0);
        float a1 = __expf(m1v - mnew1);
        m0v = mnew0; m1v = mnew1;

        uint32_t Ph[8][2], Pl[8][2];
        float rs0 = 0.f, rs1 = 0.f;
        #pragma unroll
        for (int nt = 0; nt < 8; nt++) {
            float p0 = __expf(S[nt][0] - mnew0);
            float p1 = __expf(S[nt][1] - mnew0);
            float p2 = __expf(S[nt][2] - mnew1);
            float p3 = __expf(S[nt][3] - mnew1);
            rs0 += p0 + p1;
            rs1 += p2 + p3;
            __nv_bfloat16 h0 = __float2bfloat16_rn(p0);
            __nv_bfloat16 h1 = __float2bfloat16_rn(p1);
            __nv_bfloat16 h2 = __float2bfloat16_rn(p2);
            __nv_bfloat16 h3 = __float2bfloat16_rn(p3);
            __nv_bfloat162 hA = __halves2bfloat162(h0, h1);
            __nv_bfloat162 hB = __halves2bfloat162(h2, h3);
            Ph[nt][0] = *(uint32_t*)&hA;
            Ph[nt][1] = *(uint32_t*)&hB;
            Pl[nt][0] = pack_bf16(p0 - __bfloat162float(h0), p1 - __bfloat162float(h1));
            Pl[nt][1] = pack_bf16(p2 - __bfloat162float(h2), p3 - __bfloat162float(h3));
        }
        #pragma unroll
        for (int off = 1; off <= 2; off <<= 1) {
            rs0 += __shfl_xor_sync(0xffffffffu, rs0, off);
            rs1 += __shfl_xor_sync(0xffffffffu, rs1, off);
        }
        l0v = l0v * a0 + rs0;
        l1v = l1v * a1 + rs1;
        #pragma unroll
        for (int nt = 0; nt < 8; nt++) {
            O[nt][0] *= a0; O[nt][1] *= a0;
            O[nt][2] *= a1; O[nt][3] *= a1;
        }

        // ---- O += P @ V : per-term sweeps over all 8 accumulators ----
        #pragma unroll
        for (int ks = 0; ks < 4; ks++) {
            uint32_t aH[4] = {Ph[2*ks][0], Ph[2*ks][1], Ph[2*ks+1][0], Ph[2*ks+1][1]};
            uint32_t aL[4] = {Pl[2*ks][0], Pl[2*ks][1], Pl[2*ks+1][0], Pl[2*ks+1][1]};
            uint32_t vh[4][4], vl[4][4];
            #pragma unroll
            for (int d16 = 0; d16 < 4; d16++) {
                LDMX4T(vh[d16], sb + FA_VH + lmKV + ks * (16 * FROWB) + d16 * 32);
                LDMX4T(vl[d16], sb + FA_VL + lmKV + ks * (16 * FROWB) + d16 * 32);
            }
            #pragma unroll
            for (int d16 = 0; d16 < 4; d16++) {          // Ph * Vh
                MMA16816(O[2*d16],   aH, vh[d16][0], vh[d16][1]);
                MMA16816(O[2*d16+1], aH, vh[d16][2], vh[d16][3]);
            }
            #pragma unroll
            for (int d16 = 0; d16 < 4; d16++) {          // Ph * Vl
                MMA16816(O[2*d16],   aH, vl[d16][0], vl[d16][1]);
                MMA16816(O[2*d16+1], aH, vl[d16][2], vl[d16][3]);
            }
            #pragma unroll
            for (int d16 = 0; d16 < 4; d16++) {          // Pl * Vh
                MMA16816(O[2*d16],   aL, vh[d16][0], vh[d16][1]);
                MMA16816(O[2*d16+1], aL, vh[d16][2], vh[d16][3]);
            }
        }
    }

    // ---- epilogue: normalize and write ctx[b, l, head*64 + d] ----
    const float inv0 = 1.f / l0v;
    const float inv1 = 1.f / l1v;
    const int r0 = q0 + w * 16 + g;
    const int r1 = r0 + 8;
    #pragma unroll
    for (int nt = 0; nt < 8; nt++) {
        int dd = head * HD + nt * 8 + tig * 2;
        if (r0 < SEQ) {
            float2 o = make_float2(O[nt][0] * inv0, O[nt][1] * inv0);
            *(float2*)(out + ((size_t)batch * SEQ + r0) * HID + dd) = o;
        }
        if (r1 < SEQ) {
            float2 o = make_float2(O[nt][2] * inv1, O[nt][3] * inv1);
            *(float2*)(out + ((size_t)batch * SEQ + r1) * HID + dd) = o;
        }
    }
}

// ---------------------------------------------------------------------------
// Launch
// ---------------------------------------------------------------------------
extern "C" void kernel_launch(void* const* d_in, const int* in_sizes, int n_in,
                              void* d_out, int out_size)
{
    const float* X  = (const float*)d_in[0];
    const float* Wq = (const float*)d_in[1];
    const float* bq = (const float*)d_in[2];
    const float* Wk = (const float*)d_in[3];
    const float* bk = (const float*)d_in[4];
    const float* Wv = (const float*)d_in[5];
    const float* bv = (const float*)d_in[6];
    float* out = (float*)d_out;

    cudaFuncSetAttribute(qkv_mma,   cudaFuncAttributeMaxDynamicSharedMemorySize, QK_SMEM);
    cudaFuncSetAttribute(flash_mma, cudaFuncAttributeMaxDynamicSharedMemorySize, FA_SMEM);

    dim3 g1((NTOK + 127) / 128, 24);                 // 43 x 24
    qkv_mma<<<g1, 256, QK_SMEM>>>(X, Wq, bq, Wk, bk, Wv, bv);

    dim3 g2((SEQ + 63) / 64, BATCH * NH);            // 22 x 64
    flash_mma<<<g2, 128, FA_SMEM>>>(out);
}

// round 12
// speedup vs baseline: 1.3817x; 1.3817x over previous
#include <cuda_runtime.h>
#include <cuda_fp16.h>
#include <cstdint>

#define BATCH 4
#define SEQ   1370
#define NH    16
#define HD    64
#define HID   1024
#define NTOK  (BATCH * SEQ)   // 5480

// Scratch: projected Q/K/V in [B, NH, L, HD] layout.
__device__ float g_q[(size_t)BATCH * NH * SEQ * HD];
__device__ float g_k[(size_t)BATCH * NH * SEQ * HD];
__device__ float g_v[(size_t)BATCH * NH * SEQ * HD];

// ===========================================================================
// Helpers
// ===========================================================================
__device__ __forceinline__ uint32_t smem_u32(const void* p) {
    uint32_t a;
    asm("{ .reg .u64 t; cvta.to.shared.u64 t, %1; cvt.u32.u64 %0, t; }"
        : "=r"(a) : "l"(p));
    return a;
}

#define LDMX4(r, addr) \
    asm volatile("ldmatrix.sync.aligned.m8n8.x4.shared.b16 {%0,%1,%2,%3}, [%4];" \
        : "=r"((r)[0]), "=r"((r)[1]), "=r"((r)[2]), "=r"((r)[3]) : "r"(addr))

#define LDMX4T(r, addr) \
    asm volatile("ldmatrix.sync.aligned.m8n8.x4.trans.shared.b16 {%0,%1,%2,%3}, [%4];" \
        : "=r"((r)[0]), "=r"((r)[1]), "=r"((r)[2]), "=r"((r)[3]) : "r"(addr))

#define MMA16816(d, a, b0, b1) \
    asm volatile("mma.sync.aligned.m16n8k16.row.col.f32.f16.f16.f32 " \
        "{%0,%1,%2,%3}, {%4,%5,%6,%7}, {%8,%9}, {%0,%1,%2,%3};" \
        : "+f"((d)[0]), "+f"((d)[1]), "+f"((d)[2]), "+f"((d)[3]) \
        : "r"((a)[0]), "r"((a)[1]), "r"((a)[2]), "r"((a)[3]), "r"(b0), "r"(b1))

// pack two fp32 into f16x2 (lo in low half, hi in high half)
__device__ __forceinline__ uint32_t pack_f16(float lo, float hi) {
    uint32_t r;
    asm("cvt.rn.f16x2.f32 %0, %1, %2;" : "=r"(r) : "f"(hi), "f"(lo));
    return r;
}

// fp32x4 -> exact fp16 hi/lo split, 8B to each plane.
__device__ __forceinline__ void split_sts(char* hp, char* lp, uint32_t off, float4 v) {
    __half h0 = __float2half_rn(v.x);
    __half h1 = __float2half_rn(v.y);
    __half h2 = __float2half_rn(v.z);
    __half h3 = __float2half_rn(v.w);
    float l0 = v.x - __half2float(h0);
    float l1 = v.y - __half2float(h1);
    float l2 = v.z - __half2float(h2);
    float l3 = v.w - __half2float(h3);
    uint32_t hA = pack_f16(__half2float(h0), __half2float(h1));
    uint32_t hB = pack_f16(__half2float(h2), __half2float(h3));
    *(uint2*)(hp + off) = make_uint2(hA, hB);
    *(uint2*)(lp + off) = make_uint2(pack_f16(l0, l1), pack_f16(l2, l3));
}

// fp32x4 -> rounded fp16, 8B to one plane.
__device__ __forceinline__ void round_sts(char* hp, uint32_t off, float4 v) {
    *(uint2*)(hp + off) = make_uint2(pack_f16(v.x, v.y), pack_f16(v.z, v.w));
}

// ===========================================================================
// Phase 1: QKV projection on mma.sync fp16, 2 products:
//   Y = (Xh + Xl) @ Wh^T + b   (Wh = rn_f16(W); residual = X*(W-Wh) ~ 2^-12)
// Block tile 128x128, 8 warps (4m x 2n), BK=32, double-buffered smem.
// ===========================================================================
#define QBK     32
#define QROWB   80
#define QTILE   (128 * QROWB)
#define QBUF    (3 * QTILE)          // Ah | Al | Bh = 30720 B
#define QK_SMEM (2 * QBUF)           // 61440 B
#define QCHUNKS (HID / QBK)

__global__ __launch_bounds__(256)
void qkv_mma(const float* __restrict__ X,
             const float* __restrict__ Wq, const float* __restrict__ bq,
             const float* __restrict__ Wk, const float* __restrict__ bk,
             const float* __restrict__ Wv, const float* __restrict__ bv)
{
    extern __shared__ char sm[];
    const uint32_t sbase = smem_u32(sm);

    const int tid  = threadIdx.x;
    const int lane = tid & 31;
    const int wid  = tid >> 5;
    const int wm   = wid & 3;
    const int wn   = wid >> 2;

    const int m0   = blockIdx.x * 128;
    const int nb   = blockIdx.y;
    const int proj = nb >> 3;
    const int o0   = (nb & 7) * 128;

    const float* W    = (proj == 0) ? Wq : (proj == 1) ? Wk : Wv;
    const float* bias = (proj == 0) ? bq : (proj == 1) ? bk : bv;
    float*       dst  = (proj == 0) ? g_q : (proj == 1) ? g_k : g_v;

    float acc[2][8][4];
    #pragma unroll
    for (int mt = 0; mt < 2; mt++)
        #pragma unroll
        for (int nt = 0; nt < 8; nt++)
            #pragma unroll
            for (int r = 0; r < 4; r++) acc[mt][nt][r] = 0.f;

    float4 stA[4], stB[4];
    const int ldRow = tid >> 3;
    const int ldC   = (tid & 7) << 2;

    const uint32_t lmA = (uint32_t)((wm * 32 + (lane & 15)) * QROWB + (lane >> 4) * 16);
    const uint32_t lmB = (uint32_t)((wn * 64 + (lane & 15)) * QROWB + (lane >> 4) * 16);

    #pragma unroll
    for (int i = 0; i < 4; i++) {
        int row = ldRow + i * 32;
        int gm  = m0 + row;
        stA[i] = (gm < NTOK) ? *(const float4*)(X + (size_t)gm * HID + ldC)
                             : make_float4(0.f, 0.f, 0.f, 0.f);
        stB[i] = *(const float4*)(W + (size_t)(o0 + row) * HID + ldC);
    }
    {
        char* Ah = sm; char* Al = sm + QTILE; char* Bh = sm + 2 * QTILE;
        #pragma unroll
        for (int i = 0; i < 4; i++) {
            uint32_t off = (uint32_t)((ldRow + i * 32) * QROWB + ldC * 2);
            split_sts(Ah, Al, off, stA[i]);
            round_sts(Bh, off, stB[i]);
        }
    }
    __syncthreads();

    for (int c = 0; c < QCHUNKS; c++) {
        if (c + 1 < QCHUNKS) {
            int kc = (c + 1) * QBK;
            #pragma unroll
            for (int i = 0; i < 4; i++) {
                int row = ldRow + i * 32;
                int gm  = m0 + row;
                stA[i] = (gm < NTOK) ? *(const float4*)(X + (size_t)gm * HID + kc + ldC)
                                     : make_float4(0.f, 0.f, 0.f, 0.f);
                stB[i] = *(const float4*)(W + (size_t)(o0 + row) * HID + kc + ldC);
            }
        }

        const uint32_t Ahb = sbase + (c & 1) * QBUF;
        const uint32_t Alb = Ahb + QTILE;
        const uint32_t Bhb = Ahb + 2 * QTILE;

        #pragma unroll
        for (int kk = 0; kk < 2; kk++) {
            const uint32_t kb = kk * 32;
            uint32_t fAh[2][4], fAl[2][4], fB[4][4];
            #pragma unroll
            for (int mt = 0; mt < 2; mt++) {
                LDMX4(fAh[mt], Ahb + lmA + mt * (16 * QROWB) + kb);
                LDMX4(fAl[mt], Alb + lmA + mt * (16 * QROWB) + kb);
            }
            #pragma unroll
            for (int n2 = 0; n2 < 4; n2++)
                LDMX4(fB[n2], Bhb + lmB + n2 * (16 * QROWB) + kb);
            #pragma unroll
            for (int mt = 0; mt < 2; mt++)
                #pragma unroll
                for (int nt = 0; nt < 8; nt++)     // hi * Wh
                    MMA16816(acc[mt][nt], fAh[mt], fB[nt >> 1][nt & 1], fB[nt >> 1][2 + (nt & 1)]);
            #pragma unroll
            for (int mt = 0; mt < 2; mt++)
                #pragma unroll
                for (int nt = 0; nt < 8; nt++)     // lo * Wh
                    MMA16816(acc[mt][nt], fAl[mt], fB[nt >> 1][nt & 1], fB[nt >> 1][2 + (nt & 1)]);
        }

        if (c + 1 < QCHUNKS) {
            char* Ah = sm + ((c + 1) & 1) * QBUF;
            char* Al = Ah + QTILE;
            char* Bh = Ah + 2 * QTILE;
            #pragma unroll
            for (int i = 0; i < 4; i++) {
                uint32_t off = (uint32_t)((ldRow + i * 32) * QROWB + ldC * 2);
                split_sts(Ah, Al, off, stA[i]);
                round_sts(Bh, off, stB[i]);
            }
        }
        __syncthreads();
    }

    const int g   = lane >> 2;
    const int tig = lane & 3;
    const int headBase = (o0 + wn * 64) >> 6;
    #pragma unroll
    for (int mt = 0; mt < 2; mt++) {
        #pragma unroll
        for (int half = 0; half < 2; half++) {
            int gm = m0 + wm * 32 + mt * 16 + g + half * 8;
            if (gm >= NTOK) continue;
            int bb = gm / SEQ;
            int ll = gm - bb * SEQ;
            float* dp = dst + (((size_t)bb * NH + headBase) * SEQ + ll) * HD;
            #pragma unroll
            for (int nt = 0; nt < 8; nt++) {
                int dd = nt * 8 + tig * 2;
                float2 bv = *(const float2*)(bias + o0 + wn * 64 + dd);
                float2 ov;
                ov.x = acc[mt][nt][half * 2 + 0] + bv.x;
                ov.y = acc[mt][nt][half * 2 + 1] + bv.y;
                *(float2*)(dp + dd) = ov;
            }
        }
    }
}

// ===========================================================================
// Phase 2: flash attention on mma.sync fp16, 2 products per GEMM
// (R8 geometry: 256 threads, 128 q rows, warp = m16 x 64kv/64d).
// S = (Qh+Ql) @ Kh^T ; O += (Ph+Pl) @ Vh  (K, V rounded once to fp16)
// ===========================================================================
#define FROWB 144
#define FA_QH 0
#define FA_QL (128 * FROWB)                 // 18432
#define FA_KH (2 * 128 * FROWB)             // 36864
#define FA_VH (FA_KH + 64 * FROWB)          // 46080
#define FA_SMEM (FA_VH + 64 * FROWB)        // 55296

__global__ __launch_bounds__(256)
void flash_mma(float* __restrict__ out)
{
    extern __shared__ char sm[];
    const uint32_t sb = smem_u32(sm);

    const int tid  = threadIdx.x;
    const int lane = tid & 31;
    const int w    = tid >> 5;

    const int qt    = blockIdx.x;       // 0..10
    const int bh    = blockIdx.y;       // 0..63
    const int batch = bh >> 4;
    const int head  = bh & 15;
    const float* Q = g_q + (size_t)bh * SEQ * HD;
    const float* K = g_k + (size_t)bh * SEQ * HD;
    const float* V = g_v + (size_t)bh * SEQ * HD;
    const int q0 = qt * 128;

    // Load Q tile, pre-scaled by 1/sqrt(64)=0.125, exact fp16 split.
    #pragma unroll
    for (int i = 0; i < 8; i++) {
        int f   = i * 256 + tid;
        int row = f >> 4;
        int c4  = (f & 15) << 2;
        int gq  = q0 + row;
        float4 v = (gq < SEQ)
            ? *(const float4*)(Q + (size_t)gq * HD + c4)
            : make_float4(0.f, 0.f, 0.f, 0.f);
        v.x *= 0.125f; v.y *= 0.125f; v.z *= 0.125f; v.w *= 0.125f;
        split_sts(sm + FA_QH, sm + FA_QL, (uint32_t)(row * FROWB + c4 * 2), v);
    }

    const uint32_t lmQ  = (uint32_t)((w * 16 + (lane & 15)) * FROWB + (lane >> 4) * 16);
    const uint32_t lmKV = (uint32_t)((lane & 15) * FROWB + (lane >> 4) * 16);
    const int g   = lane >> 2;
    const int tig = lane & 3;

    float m0v = -1e30f, m1v = -1e30f, l0v = 0.f, l1v = 0.f;
    float O[8][4];
    #pragma unroll
    for (int nt = 0; nt < 8; nt++)
        #pragma unroll
        for (int r = 0; r < 4; r++) O[nt][r] = 0.f;

    for (int kv0 = 0; kv0 < SEQ; kv0 += 64) {
        __syncthreads();   // prior tile's ldmatrix done (and Q stores, iter 0)

        // Load K, V tiles, round to fp16 (single plane each).
        #pragma unroll
        for (int i = 0; i < 4; i++) {
            int f   = i * 256 + tid;
            int row = f >> 4;
            int c4  = (f & 15) << 2;
            int gk  = kv0 + row;
            float4 vk, vv;
            if (gk < SEQ) {
                vk = *(const float4*)(K + (size_t)gk * HD + c4);
                vv = *(const float4*)(V + (size_t)gk * HD + c4);
            } else {
                vk = make_float4(0.f, 0.f, 0.f, 0.f);
                vv = vk;
            }
            uint32_t off = (uint32_t)(row * FROWB + c4 * 2);
            round_sts(sm + FA_KH, off, vk);
            round_sts(sm + FA_VH, off, vv);
        }
        __syncthreads();

        // ---- S = (Qh+Ql) @ Kh^T ----
        float S[8][4];
        #pragma unroll
        for (int nt = 0; nt < 8; nt++)
            #pragma unroll
            for (int r = 0; r < 4; r++) S[nt][r] = 0.f;

        #pragma unroll
        for (int ks = 0; ks < 4; ks++) {
            uint32_t qh[4], ql[4];
            LDMX4(qh, sb + FA_QH + lmQ + ks * 32);
            LDMX4(ql, sb + FA_QL + lmQ + ks * 32);
            #pragma unroll
            for (int n16 = 0; n16 < 4; n16++) {
                uint32_t kh[4];
                LDMX4(kh, sb + FA_KH + lmKV + n16 * (16 * FROWB) + ks * 32);
                MMA16816(S[2*n16],   qh, kh[0], kh[2]);
                MMA16816(S[2*n16+1], qh, kh[1], kh[3]);
                MMA16816(S[2*n16],   ql, kh[0], kh[2]);
                MMA16816(S[2*n16+1], ql, kh[1], kh[3]);
            }
        }

        // ---- key mask (last tile only) ----
        if (kv0 + 64 > SEQ) {
            #pragma unroll
            for (int nt = 0; nt < 8; nt++)
                #pragma unroll
                for (int e = 0; e < 4; e++)
                    if (kv0 + nt * 8 + tig * 2 + (e & 1) >= SEQ) S[nt][e] = -1e30f;
        }

        // ---- online softmax (rows g / g+8; reduce across quad lanes) ----
        float mx0 = -1e30f, mx1 = -1e30f;
        #pragma unroll
        for (int nt = 0; nt < 8; nt++) {
            mx0 = fmaxf(mx0, fmaxf(S[nt][0], S[nt][1]));
            mx1 = fmaxf(mx1, fmaxf(S[nt][2], S[nt][3]));
        }
        #pragma unroll
        for (int off = 1; off <= 2; off <<= 1) {
            mx0 = fmaxf(mx0, __shfl_xor_sync(0xffffffffu, mx0, off));
            mx1 = fmaxf(mx1, __shfl_xor_sync(0xffffffffu, mx1, off));
        }
        float mnew0 = fmaxf(m0v, mx0);
        float mnew1 = fmaxf(m1v, mx1);
        float a0 = __expf(m0v - mnew0);
        float a1 = __expf(m1v - mnew1);
        m0v = mnew0; m1v = mnew1;

        // P = exp(S - m), exact fp16 split in registers.
        uint32_t Ph[8][2], Pl[8][2];
        float rs0 = 0.f, rs1 = 0.f;
        #pragma unroll
        for (int nt = 0; nt < 8; nt++) {
            float p0 = __expf(S[nt][0] - mnew0);
            float p1 = __expf(S[nt][1] - mnew0);
            float p2 = __expf(S[nt][2] - mnew1);
            float p3 = __expf(S[nt][3] - mnew1);
            rs0 += p0 + p1;
            rs1 += p2 + p3;
            __half h0 = __float2half_rn(p0);
            __half h1 = __float2half_rn(p1);
            __half h2 = __float2half_rn(p2);
            __half h3 = __float2half_rn(p3);
            Ph[nt][0] = pack_f16(__half2float(h0), __half2float(h1));
            Ph[nt][1] = pack_f16(__half2float(h2), __half2float(h3));
            Pl[nt][0] = pack_f16(p0 - __half2float(h0), p1 - __half2float(h1));
            Pl[nt][1] = pack_f16(p2 - __half2float(h2), p3 - __half2float(h3));
        }
        #pragma unroll
        for (int off = 1; off <= 2; off <<= 1) {
            rs0 += __shfl_xor_sync(0xffffffffu, rs0, off);
            rs1 += __shfl_xor_sync(0xffffffffu, rs1, off);
        }
        l0v = l0v * a0 + rs0;
        l1v = l1v * a1 + rs1;
        #pragma unroll
        for (int nt = 0; nt < 8; nt++) {
            O[nt][0] *= a0; O[nt][1] *= a0;
            O[nt][2] *= a1; O[nt][3] *= a1;
        }

        // ---- O += (Ph+Pl) @ Vh ----
        #pragma unroll
        for (int ks = 0; ks < 4; ks++) {
            uint32_t aH[4] = {Ph[2*ks][0], Ph[2*ks][1], Ph[2*ks+1][0], Ph[2*ks+1][1]};
            uint32_t aL[4] = {Pl[2*ks][0], Pl[2*ks][1], Pl[2*ks+1][0], Pl[2*ks+1][1]};
            #pragma unroll
            for (int d16 = 0; d16 < 4; d16++) {
                uint32_t vh[4];
                LDMX4T(vh, sb + FA_VH + lmKV + ks * (16 * FROWB) + d16 * 32);
                MMA16816(O[2*d16],   aH, vh[0], vh[1]);
                MMA16816(O[2*d16+1], aH, vh[2], vh[3]);
                MMA16816(O[2*d16],   aL, vh[0], vh[1]);
                MMA16816(O[2*d16+1], aL, vh[2], vh[3]);
            }
        }
    }

    // ---- epilogue: normalize and write ctx[b, l, head*64 + d] ----
    const float inv0 = 1.f / l0v;
    const float inv1 = 1.f / l1v;
    const int r0 = q0 + w * 16 + g;
    const int r1 = r0 + 8;
    #pragma unroll
    for (int nt = 0; nt < 8; nt++) {
        int dd = head * HD + nt * 8 + tig * 2;
        if (r0 < SEQ) {
            float2 o = make_float2(O[nt][0] * inv0, O[nt][1] * inv0);
            *(float2*)(out + ((size_t)batch * SEQ + r0) * HID + dd) = o;
        }
        if (r1 < SEQ) {
            float2 o = make_float2(O[nt][2] * inv1, O[nt][3] * inv1);
            *(float2*)(out + ((size_t)batch * SEQ + r1) * HID + dd) = o;
        }
    }
}

// ---------------------------------------------------------------------------
// Launch
// ---------------------------------------------------------------------------
extern "C" void kernel_launch(void* const* d_in, const int* in_sizes, int n_in,
                              void* d_out, int out_size)
{
    const float* X  = (const float*)d_in[0];
    const float* Wq = (const float*)d_in[1];
    const float* bq = (const float*)d_in[2];
    const float* Wk = (const float*)d_in[3];
    const float* bk = (const float*)d_in[4];
    const float* Wv = (const float*)d_in[5];
    const float* bv = (const float*)d_in[6];
    float* out = (float*)d_out;

    cudaFuncSetAttribute(qkv_mma,   cudaFuncAttributeMaxDynamicSharedMemorySize, QK_SMEM);
    cudaFuncSetAttribute(flash_mma, cudaFuncAttributeMaxDynamicSharedMemorySize, FA_SMEM);

    dim3 g1((NTOK + 127) / 128, 24);                 // 43 x 24
    qkv_mma<<<g1, 256, QK_SMEM>>>(X, Wq, bq, Wk, bk, Wv, bv);

    dim3 g2((SEQ + 127) / 128, BATCH * NH);          // 11 x 64
    flash_mma<<<g2, 256, FA_SMEM>>>(out);
}

// round 13
// speedup vs baseline: 2.0358x; 1.4734x over previous
#include <cuda_runtime.h>
#include <cuda_fp16.h>
#include <cstdint>

#define BATCH 4
#define SEQ   1370
#define NH    16
#define HD    64
#define HID   1024
#define NTOK  (BATCH * SEQ)   // 5480
#define NELEM ((size_t)BATCH * NH * SEQ * HD)

// Scratch: projected Q/K/V in fp16 planes, [B, NH, L, HD] layout.
// Q is pre-scaled by 1/8 and exactly split (hi+lo); K, V rounded once.
__device__ __half g_qh[NELEM];
__device__ __half g_ql[NELEM];
__device__ __half g_kh[NELEM];
__device__ __half g_vh[NELEM];

// ===========================================================================
// Helpers
// ===========================================================================
__device__ __forceinline__ uint32_t smem_u32(const void* p) {
    uint32_t a;
    asm("{ .reg .u64 t; cvta.to.shared.u64 t, %1; cvt.u32.u64 %0, t; }"
        : "=r"(a) : "l"(p));
    return a;
}

#define LDMX4(r, addr) \
    asm volatile("ldmatrix.sync.aligned.m8n8.x4.shared.b16 {%0,%1,%2,%3}, [%4];" \
        : "=r"((r)[0]), "=r"((r)[1]), "=r"((r)[2]), "=r"((r)[3]) : "r"(addr))

#define LDMX4T(r, addr) \
    asm volatile("ldmatrix.sync.aligned.m8n8.x4.trans.shared.b16 {%0,%1,%2,%3}, [%4];" \
        : "=r"((r)[0]), "=r"((r)[1]), "=r"((r)[2]), "=r"((r)[3]) : "r"(addr))

#define MMA16816(d, a, b0, b1) \
    asm volatile("mma.sync.aligned.m16n8k16.row.col.f32.f16.f16.f32 " \
        "{%0,%1,%2,%3}, {%4,%5,%6,%7}, {%8,%9}, {%0,%1,%2,%3};" \
        : "+f"((d)[0]), "+f"((d)[1]), "+f"((d)[2]), "+f"((d)[3]) \
        : "r"((a)[0]), "r"((a)[1]), "r"((a)[2]), "r"((a)[3]), "r"(b0), "r"(b1))

__device__ __forceinline__ uint32_t pack_f16(float lo, float hi) {
    uint32_t r;
    asm("cvt.rn.f16x2.f32 %0, %1, %2;" : "=r"(r) : "f"(hi), "f"(lo));
    return r;
}

// fp32x4 -> rounded fp16, 8B to one plane.
__device__ __forceinline__ void round_sts(char* hp, uint32_t off, float4 v) {
    *(uint2*)(hp + off) = make_uint2(pack_f16(v.x, v.y), pack_f16(v.z, v.w));
}

// ===========================================================================
// Phase 1: QKV projection, pure fp16 mma.sync:  Y = rn(X) @ rn(W)^T + b.
// Block tile 128x128, 8 warps (4m x 2n), BK=32, double-buffered smem.
// Epilogue writes fp16 planes: Q scaled 1/8 + exact hi/lo split; K,V rounded.
// ===========================================================================
#define QBK     32
#define QROWB   80
#define QTILE   (128 * QROWB)        // 10240
#define QBUF    (2 * QTILE)          // Ah | Bh = 20480
#define QK_SMEM (2 * QBUF)           // 40960
#define QCHUNKS (HID / QBK)

__global__ __launch_bounds__(256)
void qkv_mma(const float* __restrict__ X,
             const float* __restrict__ Wq, const float* __restrict__ bq,
             const float* __restrict__ Wk, const float* __restrict__ bk,
             const float* __restrict__ Wv, const float* __restrict__ bv)
{
    extern __shared__ char sm[];
    const uint32_t sbase = smem_u32(sm);

    const int tid  = threadIdx.x;
    const int lane = tid & 31;
    const int wid  = tid >> 5;
    const int wm   = wid & 3;
    const int wn   = wid >> 2;

    const int m0   = blockIdx.x * 128;
    const int nb   = blockIdx.y;
    const int proj = nb >> 3;
    const int o0   = (nb & 7) * 128;

    const float* W    = (proj == 0) ? Wq : (proj == 1) ? Wk : Wv;
    const float* bias = (proj == 0) ? bq : (proj == 1) ? bk : bv;

    float acc[2][8][4];
    #pragma unroll
    for (int mt = 0; mt < 2; mt++)
        #pragma unroll
        for (int nt = 0; nt < 8; nt++)
            #pragma unroll
            for (int r = 0; r < 4; r++) acc[mt][nt][r] = 0.f;

    float4 stA[4], stB[4];
    const int ldRow = tid >> 3;
    const int ldC   = (tid & 7) << 2;

    const uint32_t lmA = (uint32_t)((wm * 32 + (lane & 15)) * QROWB + (lane >> 4) * 16);
    const uint32_t lmB = (uint32_t)((wn * 64 + (lane & 15)) * QROWB + (lane >> 4) * 16);

    #pragma unroll
    for (int i = 0; i < 4; i++) {
        int row = ldRow + i * 32;
        int gm  = m0 + row;
        stA[i] = (gm < NTOK) ? *(const float4*)(X + (size_t)gm * HID + ldC)
                             : make_float4(0.f, 0.f, 0.f, 0.f);
        stB[i] = *(const float4*)(W + (size_t)(o0 + row) * HID + ldC);
    }
    {
        char* Ah = sm; char* Bh = sm + QTILE;
        #pragma unroll
        for (int i = 0; i < 4; i++) {
            uint32_t off = (uint32_t)((ldRow + i * 32) * QROWB + ldC * 2);
            round_sts(Ah, off, stA[i]);
            round_sts(Bh, off, stB[i]);
        }
    }
    __syncthreads();

    for (int c = 0; c < QCHUNKS; c++) {
        if (c + 1 < QCHUNKS) {
            int kc = (c + 1) * QBK;
            #pragma unroll
            for (int i = 0; i < 4; i++) {
                int row = ldRow + i * 32;
                int gm  = m0 + row;
                stA[i] = (gm < NTOK) ? *(const float4*)(X + (size_t)gm * HID + kc + ldC)
                                     : make_float4(0.f, 0.f, 0.f, 0.f);
                stB[i] = *(const float4*)(W + (size_t)(o0 + row) * HID + kc + ldC);
            }
        }

        const uint32_t Ahb = sbase + (c & 1) * QBUF;
        const uint32_t Bhb = Ahb + QTILE;

        #pragma unroll
        for (int kk = 0; kk < 2; kk++) {
            const uint32_t kb = kk * 32;
            uint32_t fAh[2][4], fB[4][4];
            #pragma unroll
            for (int mt = 0; mt < 2; mt++)
                LDMX4(fAh[mt], Ahb + lmA + mt * (16 * QROWB) + kb);
            #pragma unroll
            for (int n2 = 0; n2 < 4; n2++)
                LDMX4(fB[n2], Bhb + lmB + n2 * (16 * QROWB) + kb);
            #pragma unroll
            for (int mt = 0; mt < 2; mt++)
                #pragma unroll
                for (int nt = 0; nt < 8; nt++)
                    MMA16816(acc[mt][nt], fAh[mt], fB[nt >> 1][nt & 1], fB[nt >> 1][2 + (nt & 1)]);
        }

        if (c + 1 < QCHUNKS) {
            char* Ah = sm + ((c + 1) & 1) * QBUF;
            char* Bh = Ah + QTILE;
            #pragma unroll
            for (int i = 0; i < 4; i++) {
                uint32_t off = (uint32_t)((ldRow + i * 32) * QROWB + ldC * 2);
                round_sts(Ah, off, stA[i]);
                round_sts(Bh, off, stB[i]);
            }
        }
        __syncthreads();
    }

    // ---- epilogue: bias add, convert to fp16 planes, scatter [B,NH,L,HD] ----
    const int g   = lane >> 2;
    const int tig = lane & 3;
    const int headBase = (o0 + wn * 64) >> 6;
    #pragma unroll
    for (int mt = 0; mt < 2; mt++) {
        #pragma unroll
        for (int half = 0; half < 2; half++) {
            int gm = m0 + wm * 32 + mt * 16 + g + half * 8;
            if (gm >= NTOK) continue;
            int bb = gm / SEQ;
            int ll = gm - bb * SEQ;
            size_t base = (((size_t)bb * NH + headBase) * SEQ + ll) * HD;
            #pragma unroll
            for (int nt = 0; nt < 8; nt++) {
                int dd = nt * 8 + tig * 2;
                float2 bv = *(const float2*)(bias + o0 + wn * 64 + dd);
                float v0 = acc[mt][nt][half * 2 + 0] + bv.x;
                float v1 = acc[mt][nt][half * 2 + 1] + bv.y;
                if (proj == 0) {
                    v0 *= 0.125f; v1 *= 0.125f;       // fold softmax scale into Q
                    __half h0 = __float2half_rn(v0);
                    __half h1 = __float2half_rn(v1);
                    *(uint32_t*)(g_qh + base + dd) =
                        pack_f16(__half2float(h0), __half2float(h1));
                    *(uint32_t*)(g_ql + base + dd) =
                        pack_f16(v0 - __half2float(h0), v1 - __half2float(h1));
                } else {
                    __half* dp = (proj == 1) ? g_kh : g_vh;
                    *(uint32_t*)(dp + base + dd) = pack_f16(v0, v1);
                }
            }
        }
    }
}

// ===========================================================================
// Phase 2: flash attention on fp16 mma.sync, fp16-native inputs.
// 256 threads, 128 q rows, warp = m16 x 64kv/64d.
// S = (Qh+Ql) @ Kh^T  (2 products);  O += Ph @ Vh  (1 product — P >= 0,
// positive weighted average: dropping Pl is well-conditioned).
// ===========================================================================
#define FROWB 144
#define FA_QH 0
#define FA_QL (128 * FROWB)                 // 18432
#define FA_KH (2 * 128 * FROWB)             // 36864
#define FA_VH (FA_KH + 64 * FROWB)          // 46080
#define FA_SMEM (FA_VH + 64 * FROWB)        // 55296

__global__ __launch_bounds__(256)
void flash_mma(float* __restrict__ out)
{
    extern __shared__ char sm[];
    const uint32_t sb = smem_u32(sm);

    const int tid  = threadIdx.x;
    const int lane = tid & 31;
    const int w    = tid >> 5;

    const int qt    = blockIdx.x;       // 0..10
    const int bh    = blockIdx.y;       // 0..63
    const int batch = bh >> 4;
    const int head  = bh & 15;
    const __half* Qh = g_qh + (size_t)bh * SEQ * HD;
    const __half* Ql = g_ql + (size_t)bh * SEQ * HD;
    const __half* Kh = g_kh + (size_t)bh * SEQ * HD;
    const __half* Vh = g_vh + (size_t)bh * SEQ * HD;
    const int q0 = qt * 128;

    // Load Q planes (fp16, already scaled+split): 2 x 128 rows x 128B.
    #pragma unroll
    for (int i = 0; i < 8; i++) {
        int f     = i * 256 + tid;          // 0..2047 16B-chunk ids
        int plane = f >> 10;                // 0=hi, 1=lo
        int p     = f & 1023;
        int row   = p >> 3;
        int seg   = p & 7;                  // 16B unit within 128B row
        int gq    = q0 + row;
        const __half* src = (plane ? Ql : Qh) + (size_t)gq * HD + seg * 8;
        uint4 v = (gq < SEQ) ? *(const uint4*)src : make_uint4(0u, 0u, 0u, 0u);
        *(uint4*)(sm + (plane ? FA_QL : FA_QH) + row * FROWB + seg * 16) = v;
    }

    const uint32_t lmQ  = (uint32_t)((w * 16 + (lane & 15)) * FROWB + (lane >> 4) * 16);
    const uint32_t lmKV = (uint32_t)((lane & 15) * FROWB + (lane >> 4) * 16);
    const int g   = lane >> 2;
    const int tig = lane & 3;

    float m0v = -1e30f, m1v = -1e30f, l0v = 0.f, l1v = 0.f;
    float O[8][4];
    #pragma unroll
    for (int nt = 0; nt < 8; nt++)
        #pragma unroll
        for (int r = 0; r < 4; r++) O[nt][r] = 0.f;

    for (int kv0 = 0; kv0 < SEQ; kv0 += 64) {
        __syncthreads();   // prior tile's ldmatrix done (and Q stores, iter 0)

        // Load K, V tiles (fp16 native): 2 x 64 rows x 128B.
        #pragma unroll
        for (int i = 0; i < 4; i++) {
            int f   = i * 256 + tid;        // 0..1023
            int arr = f >> 9;               // 0=K, 1=V
            int p   = f & 511;
            int row = p >> 3;
            int seg = p & 7;
            int gk  = kv0 + row;
            const __half* src = (arr ? Vh : Kh) + (size_t)gk * HD + seg * 8;
            uint4 v = (gk < SEQ) ? *(const uint4*)src : make_uint4(0u, 0u, 0u, 0u);
            *(uint4*)(sm + (arr ? FA_VH : FA_KH) + row * FROWB + seg * 16) = v;
        }
        __syncthreads();

        // ---- S = (Qh+Ql) @ Kh^T ----
        float S[8][4];
        #pragma unroll
        for (int nt = 0; nt < 8; nt++)
            #pragma unroll
            for (int r = 0; r < 4; r++) S[nt][r] = 0.f;

        #pragma unroll
        for (int ks = 0; ks < 4; ks++) {
            uint32_t qh[4], ql[4];
            LDMX4(qh, sb + FA_QH + lmQ + ks * 32);
            LDMX4(ql, sb + FA_QL + lmQ + ks * 32);
            #pragma unroll
            for (int n16 = 0; n16 < 4; n16++) {
                uint32_t kh[4];
                LDMX4(kh, sb + FA_KH + lmKV + n16 * (16 * FROWB) + ks * 32);
                MMA16816(S[2*n16],   qh, kh[0], kh[2]);
                MMA16816(S[2*n16+1], qh, kh[1], kh[3]);
                MMA16816(S[2*n16],   ql, kh[0], kh[2]);
                MMA16816(S[2*n16+1], ql, kh[1], kh[3]);
            }
        }

        // ---- key mask (last tile only) ----
        if (kv0 + 64 > SEQ) {
            #pragma unroll
            for (int nt = 0; nt < 8; nt++)
                #pragma unroll
                for (int e = 0; e < 4; e++)
                    if (kv0 + nt * 8 + tig * 2 + (e & 1) >= SEQ) S[nt][e] = -1e30f;
        }

        // ---- online softmax (rows g / g+8; reduce across quad lanes) ----
        float mx0 = -1e30f, mx1 = -1e30f;
        #pragma unroll
        for (int nt = 0; nt < 8; nt++) {
            mx0 = fmaxf(mx0, fmaxf(S[nt][0], S[nt][1]));
            mx1 = fmaxf(mx1, fmaxf(S[nt][2], S[nt][3]));
        }
        #pragma unroll
        for (int off = 1; off <= 2; off <<= 1) {
            mx0 = fmaxf(mx0, __shfl_xor_sync(0xffffffffu, mx0, off));
            mx1 = fmaxf(mx1, __shfl_xor_sync(0xffffffffu, mx1, off));
        }
        float mnew0 = fmaxf(m0v, mx0);
        float mnew1 = fmaxf(m1v, mx1);
        float a0 = __expf(m0v - mnew0);
        float a1 = __expf(m1v - mnew1);
        m0v = mnew0; m1v = mnew1;

        uint32_t Ph[8][2];
        float rs0 = 0.f, rs1 = 0.f;
        #pragma unroll
        for (int nt = 0; nt < 8; nt++) {
            float p0 = __expf(S[nt][0] - mnew0);
            float p1 = __expf(S[nt][1] - mnew0);
            float p2 = __expf(S[nt][2] - mnew1);
            float p3 = __expf(S[nt][3] - mnew1);
            rs0 += p0 + p1;
            rs1 += p2 + p3;
            Ph[nt][0] = pack_f16(p0, p1);
            Ph[nt][1] = pack_f16(p2, p3);
        }
        #pragma unroll
        for (int off = 1; off <= 2; off <<= 1) {
            rs0 += __shfl_xor_sync(0xffffffffu, rs0, off);
            rs1 += __shfl_xor_sync(0xffffffffu, rs1, off);
        }
        l0v = l0v * a0 + rs0;
        l1v = l1v * a1 + rs1;
        #pragma unroll
        for (int nt = 0; nt < 8; nt++) {
            O[nt][0] *= a0; O[nt][1] *= a0;
            O[nt][2] *= a1; O[nt][3] *= a1;
        }

        // ---- O += Ph @ Vh ----
        #pragma unroll
        for (int ks = 0; ks < 4; ks++) {
            uint32_t aH[4] = {Ph[2*ks][0], Ph[2*ks][1], Ph[2*ks+1][0], Ph[2*ks+1][1]};
            #pragma unroll
            for (int d16 = 0; d16 < 4; d16++) {
                uint32_t vh[4];
                LDMX4T(vh, sb + FA_VH + lmKV + ks * (16 * FROWB) + d16 * 32);
                MMA16816(O[2*d16],   aH, vh[0], vh[1]);
                MMA16816(O[2*d16+1], aH, vh[2], vh[3]);
            }
        }
    }

    // ---- epilogue: normalize and write ctx[b, l, head*64 + d] ----
    const float inv0 = 1.f / l0v;
    const float inv1 = 1.f / l1v;
    const int r0 = q0 + w * 16 + g;
    const int r1 = r0 + 8;
    #pragma unroll
    for (int nt = 0; nt < 8; nt++) {
        int dd = head * HD + nt * 8 + tig * 2;
        if (r0 < SEQ) {
            float2 o = make_float2(O[nt][0] * inv0, O[nt][1] * inv0);
            *(float2*)(out + ((size_t)batch * SEQ + r0) * HID + dd) = o;
        }
        if (r1 < SEQ) {
            float2 o = make_float2(O[nt][2] * inv1, O[nt][3] * inv1);
            *(float2*)(out + ((size_t)batch * SEQ + r1) * HID + dd) = o;
        }
    }
}

// ---------------------------------------------------------------------------
// Launch
// ---------------------------------------------------------------------------
extern "C" void kernel_launch(void* const* d_in, const int* in_sizes, int n_in,
                              void* d_out, int out_size)
{
    const float* X  = (const float*)d_in[0];
    const float* Wq = (const float*)d_in[1];
    const float* bq = (const float*)d_in[2];
    const float* Wk = (const float*)d_in[3];
    const float* bk = (const float*)d_in[4];
    const float* Wv = (const float*)d_in[5];
    const float* bv = (const float*)d_in[6];
    float* out = (float*)d_out;

    cudaFuncSetAttribute(qkv_mma,   cudaFuncAttributeMaxDynamicSharedMemorySize, QK_SMEM);
    cudaFuncSetAttribute(flash_mma, cudaFuncAttributeMaxDynamicSharedMemorySize, FA_SMEM);

    dim3 g1((NTOK + 127) / 128, 24);                 // 43 x 24
    qkv_mma<<<g1, 256, QK_SMEM>>>(X, Wq, bq, Wk, bk, Wv, bv);

    dim3 g2((SEQ + 127) / 128, BATCH * NH);          // 11 x 64
    flash_mma<<<g2, 256, FA_SMEM>>>(out);
}

// round 14
// speedup vs baseline: 2.3419x; 1.1504x over previous
#include <cuda_runtime.h>
#include <cuda_fp16.h>
#include <cstdint>

#define BATCH 4
#define SEQ   1370
#define NH    16
#define HD    64
#define HID   1024
#define NTOK  (BATCH * SEQ)   // 5480
#define NELEM ((size_t)BATCH * NH * SEQ * HD)

// Q scale: 1/sqrt(64) * log2(e)  (folded so softmax can use exp2)
#define QSCALE (0.125f * 1.44269504088896f)

// Scratch: projected Q/K/V as fp16, [B, NH, L, HD] layout.
__device__ __half g_qh[NELEM];
__device__ __half g_kh[NELEM];
__device__ __half g_vh[NELEM];

// ===========================================================================
// Helpers
// ===========================================================================
__device__ __forceinline__ uint32_t smem_u32(const void* p) {
    uint32_t a;
    asm("{ .reg .u64 t; cvta.to.shared.u64 t, %1; cvt.u32.u64 %0, t; }"
        : "=r"(a) : "l"(p));
    return a;
}

#define LDMX4(r, addr) \
    asm volatile("ldmatrix.sync.aligned.m8n8.x4.shared.b16 {%0,%1,%2,%3}, [%4];" \
        : "=r"((r)[0]), "=r"((r)[1]), "=r"((r)[2]), "=r"((r)[3]) : "r"(addr))

#define LDMX4T(r, addr) \
    asm volatile("ldmatrix.sync.aligned.m8n8.x4.trans.shared.b16 {%0,%1,%2,%3}, [%4];" \
        : "=r"((r)[0]), "=r"((r)[1]), "=r"((r)[2]), "=r"((r)[3]) : "r"(addr))

#define MMA16816(d, a, b0, b1) \
    asm volatile("mma.sync.aligned.m16n8k16.row.col.f32.f16.f16.f32 " \
        "{%0,%1,%2,%3}, {%4,%5,%6,%7}, {%8,%9}, {%0,%1,%2,%3};" \
        : "+f"((d)[0]), "+f"((d)[1]), "+f"((d)[2]), "+f"((d)[3]) \
        : "r"((a)[0]), "r"((a)[1]), "r"((a)[2]), "r"((a)[3]), "r"(b0), "r"(b1))

__device__ __forceinline__ uint32_t pack_f16(float lo, float hi) {
    uint32_t r;
    asm("cvt.rn.f16x2.f32 %0, %1, %2;" : "=r"(r) : "f"(hi), "f"(lo));
    return r;
}

// fp32x4 -> rounded fp16, 8B to one plane.
__device__ __forceinline__ void round_sts(char* hp, uint32_t off, float4 v) {
    *(uint2*)(hp + off) = make_uint2(pack_f16(v.x, v.y), pack_f16(v.z, v.w));
}

// ===========================================================================
// Phase 1: QKV projection, pure fp16 mma.sync:  Y = rn(X) @ rn(W)^T + b.
// Block tile 128x128, 8 warps (4m x 2n), BK=32, double-buffered smem.
// Epilogue writes fp16: Q pre-scaled by QSCALE, K/V plain; all rounded once.
// ===========================================================================
#define QBK     32
#define QROWB   80
#define QTILE   (128 * QROWB)        // 10240
#define QBUF    (2 * QTILE)          // Ah | Bh = 20480
#define QK_SMEM (2 * QBUF)           // 40960
#define QCHUNKS (HID / QBK)

__global__ __launch_bounds__(256)
void qkv_mma(const float* __restrict__ X,
             const float* __restrict__ Wq, const float* __restrict__ bq,
             const float* __restrict__ Wk, const float* __restrict__ bk,
             const float* __restrict__ Wv, const float* __restrict__ bv)
{
    extern __shared__ char sm[];
    const uint32_t sbase = smem_u32(sm);

    const int tid  = threadIdx.x;
    const int lane = tid & 31;
    const int wid  = tid >> 5;
    const int wm   = wid & 3;
    const int wn   = wid >> 2;

    const int m0   = blockIdx.x * 128;
    const int nb   = blockIdx.y;
    const int proj = nb >> 3;
    const int o0   = (nb & 7) * 128;

    const float* W    = (proj == 0) ? Wq : (proj == 1) ? Wk : Wv;
    const float* bias = (proj == 0) ? bq : (proj == 1) ? bk : bv;

    float acc[2][8][4];
    #pragma unroll
    for (int mt = 0; mt < 2; mt++)
        #pragma unroll
        for (int nt = 0; nt < 8; nt++)
            #pragma unroll
            for (int r = 0; r < 4; r++) acc[mt][nt][r] = 0.f;

    float4 stA[4], stB[4];
    const int ldRow = tid >> 3;
    const int ldC   = (tid & 7) << 2;

    const uint32_t lmA = (uint32_t)((wm * 32 + (lane & 15)) * QROWB + (lane >> 4) * 16);
    const uint32_t lmB = (uint32_t)((wn * 64 + (lane & 15)) * QROWB + (lane >> 4) * 16);

    #pragma unroll
    for (int i = 0; i < 4; i++) {
        int row = ldRow + i * 32;
        int gm  = m0 + row;
        stA[i] = (gm < NTOK) ? *(const float4*)(X + (size_t)gm * HID + ldC)
                             : make_float4(0.f, 0.f, 0.f, 0.f);
        stB[i] = *(const float4*)(W + (size_t)(o0 + row) * HID + ldC);
    }
    {
        char* Ah = sm; char* Bh = sm + QTILE;
        #pragma unroll
        for (int i = 0; i < 4; i++) {
            uint32_t off = (uint32_t)((ldRow + i * 32) * QROWB + ldC * 2);
            round_sts(Ah, off, stA[i]);
            round_sts(Bh, off, stB[i]);
        }
    }
    __syncthreads();

    for (int c = 0; c < QCHUNKS; c++) {
        if (c + 1 < QCHUNKS) {
            int kc = (c + 1) * QBK;
            #pragma unroll
            for (int i = 0; i < 4; i++) {
                int row = ldRow + i * 32;
                int gm  = m0 + row;
                stA[i] = (gm < NTOK) ? *(const float4*)(X + (size_t)gm * HID + kc + ldC)
                                     : make_float4(0.f, 0.f, 0.f, 0.f);
                stB[i] = *(const float4*)(W + (size_t)(o0 + row) * HID + kc + ldC);
            }
        }

        const uint32_t Ahb = sbase + (c & 1) * QBUF;
        const uint32_t Bhb = Ahb + QTILE;

        #pragma unroll
        for (int kk = 0; kk < 2; kk++) {
            const uint32_t kb = kk * 32;
            uint32_t fAh[2][4], fB[4][4];
            #pragma unroll
            for (int mt = 0; mt < 2; mt++)
                LDMX4(fAh[mt], Ahb + lmA + mt * (16 * QROWB) + kb);
            #pragma unroll
            for (int n2 = 0; n2 < 4; n2++)
                LDMX4(fB[n2], Bhb + lmB + n2 * (16 * QROWB) + kb);
            #pragma unroll
            for (int mt = 0; mt < 2; mt++)
                #pragma unroll
                for (int nt = 0; nt < 8; nt++)
                    MMA16816(acc[mt][nt], fAh[mt], fB[nt >> 1][nt & 1], fB[nt >> 1][2 + (nt & 1)]);
        }

        if (c + 1 < QCHUNKS) {
            char* Ah = sm + ((c + 1) & 1) * QBUF;
            char* Bh = Ah + QTILE;
            #pragma unroll
            for (int i = 0; i < 4; i++) {
                uint32_t off = (uint32_t)((ldRow + i * 32) * QROWB + ldC * 2);
                round_sts(Ah, off, stA[i]);
                round_sts(Bh, off, stB[i]);
            }
        }
        __syncthreads();
    }

    // ---- epilogue: bias add, fp16 round, scatter [B,NH,L,HD] ----
    const int g   = lane >> 2;
    const int tig = lane & 3;
    const int headBase = (o0 + wn * 64) >> 6;
    __half* dp0 = (proj == 0) ? g_qh : (proj == 1) ? g_kh : g_vh;
    const float sc = (proj == 0) ? QSCALE : 1.f;
    #pragma unroll
    for (int mt = 0; mt < 2; mt++) {
        #pragma unroll
        for (int half = 0; half < 2; half++) {
            int gm = m0 + wm * 32 + mt * 16 + g + half * 8;
            if (gm >= NTOK) continue;
            int bb = gm / SEQ;
            int ll = gm - bb * SEQ;
            size_t base = (((size_t)bb * NH + headBase) * SEQ + ll) * HD;
            #pragma unroll
            for (int nt = 0; nt < 8; nt++) {
                int dd = nt * 8 + tig * 2;
                float2 bv = *(const float2*)(bias + o0 + wn * 64 + dd);
                float v0 = (acc[mt][nt][half * 2 + 0] + bv.x) * sc;
                float v1 = (acc[mt][nt][half * 2 + 1] + bv.y) * sc;
                *(uint32_t*)(dp0 + base + dd) = pack_f16(v0, v1);
            }
        }
    }
}

// ===========================================================================
// Phase 2: flash attention, pure fp16 mma.sync, fp16-native inputs.
// 256 threads, 128 q rows, warp = m16 x 64kv/64d.
// S = Qh @ Kh^T (log2-domain, Q pre-scaled by 0.125*log2e); softmax via exp2.
// O += Ph @ Vh.
// ===========================================================================
#define FROWB 144
#define FA_QH 0
#define FA_KH (128 * FROWB)                 // 18432
#define FA_VH (FA_KH + 64 * FROWB)          // 27648
#define FA_SMEM (FA_VH + 64 * FROWB)        // 36864

__global__ __launch_bounds__(256)
void flash_mma(float* __restrict__ out)
{
    extern __shared__ char sm[];
    const uint32_t sb = smem_u32(sm);

    const int tid  = threadIdx.x;
    const int lane = tid & 31;
    const int w    = tid >> 5;

    const int qt    = blockIdx.x;       // 0..10
    const int bh    = blockIdx.y;       // 0..63
    const int batch = bh >> 4;
    const int head  = bh & 15;
    const __half* Qh = g_qh + (size_t)bh * SEQ * HD;
    const __half* Kh = g_kh + (size_t)bh * SEQ * HD;
    const __half* Vh = g_vh + (size_t)bh * SEQ * HD;
    const int q0 = qt * 128;

    // Load Q plane (fp16, pre-scaled): 128 rows x 128B.
    #pragma unroll
    for (int i = 0; i < 4; i++) {
        int f   = i * 256 + tid;            // 0..1023 16B-chunk ids
        int row = f >> 3;
        int seg = f & 7;
        int gq  = q0 + row;
        const __half* src = Qh + (size_t)gq * HD + seg * 8;
        uint4 v = (gq < SEQ) ? *(const uint4*)src : make_uint4(0u, 0u, 0u, 0u);
        *(uint4*)(sm + FA_QH + row * FROWB + seg * 16) = v;
    }

    const uint32_t lmQ  = (uint32_t)((w * 16 + (lane & 15)) * FROWB + (lane >> 4) * 16);
    const uint32_t lmKV = (uint32_t)((lane & 15) * FROWB + (lane >> 4) * 16);
    const int g   = lane >> 2;
    const int tig = lane & 3;

    float m0v = -1e30f, m1v = -1e30f, l0v = 0.f, l1v = 0.f;
    float O[8][4];
    #pragma unroll
    for (int nt = 0; nt < 8; nt++)
        #pragma unroll
        for (int r = 0; r < 4; r++) O[nt][r] = 0.f;

    for (int kv0 = 0; kv0 < SEQ; kv0 += 64) {
        __syncthreads();   // prior tile's ldmatrix done (and Q stores, iter 0)

        // Load K, V tiles (fp16 native): 2 x 64 rows x 128B.
        #pragma unroll
        for (int i = 0; i < 4; i++) {
            int f   = i * 256 + tid;        // 0..1023
            int arr = f >> 9;               // 0=K, 1=V
            int p   = f & 511;
            int row = p >> 3;
            int seg = p & 7;
            int gk  = kv0 + row;
            const __half* src = (arr ? Vh : Kh) + (size_t)gk * HD + seg * 8;
            uint4 v = (gk < SEQ) ? *(const uint4*)src : make_uint4(0u, 0u, 0u, 0u);
            *(uint4*)(sm + (arr ? FA_VH : FA_KH) + row * FROWB + seg * 16) = v;
        }
        __syncthreads();

        // ---- S = Qh @ Kh^T (log2 domain) ----
        float S[8][4];
        #pragma unroll
        for (int nt = 0; nt < 8; nt++)
            #pragma unroll
            for (int r = 0; r < 4; r++) S[nt][r] = 0.f;

        #pragma unroll
        for (int ks = 0; ks < 4; ks++) {
            uint32_t qh[4];
            LDMX4(qh, sb + FA_QH + lmQ + ks * 32);
            #pragma unroll
            for (int n16 = 0; n16 < 4; n16++) {
                uint32_t kh[4];
                LDMX4(kh, sb + FA_KH + lmKV + n16 * (16 * FROWB) + ks * 32);
                MMA16816(S[2*n16],   qh, kh[0], kh[2]);
                MMA16816(S[2*n16+1], qh, kh[1], kh[3]);
            }
        }

        // ---- key mask (last tile only) ----
        if (kv0 + 64 > SEQ) {
            #pragma unroll
            for (int nt = 0; nt < 8; nt++)
                #pragma unroll
                for (int e = 0; e < 4; e++)
                    if (kv0 + nt * 8 + tig * 2 + (e & 1) >= SEQ) S[nt][e] = -1e30f;
        }

        // ---- online softmax, base-2 (rows g / g+8; quad reduction) ----
        float mx0 = -1e30f, mx1 = -1e30f;
        #pragma unroll
        for (int nt = 0; nt < 8; nt++) {
            mx0 = fmaxf(mx0, fmaxf(S[nt][0], S[nt][1]));
            mx1 = fmaxf(mx1, fmaxf(S[nt][2], S[nt][3]));
        }
        #pragma unroll
        for (int off = 1; off <= 2; off <<= 1) {
            mx0 = fmaxf(mx0, __shfl_xor_sync(0xffffffffu, mx0, off));
            mx1 = fmaxf(mx1, __shfl_xor_sync(0xffffffffu, mx1, off));
        }
        float mnew0 = fmaxf(m0v, mx0);
        float mnew1 = fmaxf(m1v, mx1);
        float a0 = exp2f(m0v - mnew0);
        float a1 = exp2f(m1v - mnew1);
        m0v = mnew0; m1v = mnew1;

        uint32_t Ph[8][2];
        float rs0 = 0.f, rs1 = 0.f;
        #pragma unroll
        for (int nt = 0; nt < 8; nt++) {
            float p0 = exp2f(S[nt][0] - mnew0);
            float p1 = exp2f(S[nt][1] - mnew0);
            float p2 = exp2f(S[nt][2] - mnew1);
            float p3 = exp2f(S[nt][3] - mnew1);
            rs0 += p0 + p1;
            rs1 += p2 + p3;
            Ph[nt][0] = pack_f16(p0, p1);
            Ph[nt][1] = pack_f16(p2, p3);
        }
        #pragma unroll
        for (int off = 1; off <= 2; off <<= 1) {
            rs0 += __shfl_xor_sync(0xffffffffu, rs0, off);
            rs1 += __shfl_xor_sync(0xffffffffu, rs1, off);
        }
        l0v = l0v * a0 + rs0;
        l1v = l1v * a1 + rs1;
        #pragma unroll
        for (int nt = 0; nt < 8; nt++) {
            O[nt][0] *= a0; O[nt][1] *= a0;
            O[nt][2] *= a1; O[nt][3] *= a1;
        }

        // ---- O += Ph @ Vh ----
        #pragma unroll
        for (int ks = 0; ks < 4; ks++) {
            uint32_t aH[4] = {Ph[2*ks][0], Ph[2*ks][1], Ph[2*ks+1][0], Ph[2*ks+1][1]};
            #pragma unroll
            for (int d16 = 0; d16 < 4; d16++) {
                uint32_t vh[4];
                LDMX4T(vh, sb + FA_VH + lmKV + ks * (16 * FROWB) + d16 * 32);
                MMA16816(O[2*d16],   aH, vh[0], vh[1]);
                MMA16816(O[2*d16+1], aH, vh[2], vh[3]);
            }
        }
    }

    // ---- epilogue: normalize and write ctx[b, l, head*64 + d] ----
    const float inv0 = 1.f / l0v;
    const float inv1 = 1.f / l1v;
    const int r0 = q0 + w * 16 + g;
    const int r1 = r0 + 8;
    #pragma unroll
    for (int nt = 0; nt < 8; nt++) {
        int dd = head * HD + nt * 8 + tig * 2;
        if (r0 < SEQ) {
            float2 o = make_float2(O[nt][0] * inv0, O[nt][1] * inv0);
            *(float2*)(out + ((size_t)batch * SEQ + r0) * HID + dd) = o;
        }
        if (r1 < SEQ) {
            float2 o = make_float2(O[nt][2] * inv1, O[nt][3] * inv1);
            *(float2*)(out + ((size_t)batch * SEQ + r1) * HID + dd) = o;
        }
    }
}

// ---------------------------------------------------------------------------
// Launch
// ---------------------------------------------------------------------------
extern "C" void kernel_launch(void* const* d_in, const int* in_sizes, int n_in,
                              void* d_out, int out_size)
{
    const float* X  = (const float*)d_in[0];
    const float* Wq = (const float*)d_in[1];
    const float* bq = (const float*)d_in[2];
    const float* Wk = (const float*)d_in[3];
    const float* bk = (const float*)d_in[4];
    const float* Wv = (const float*)d_in[5];
    const float* bv = (const float*)d_in[6];
    float* out = (float*)d_out;

    cudaFuncSetAttribute(qkv_mma,   cudaFuncAttributeMaxDynamicSharedMemorySize, QK_SMEM);
    cudaFuncSetAttribute(flash_mma, cudaFuncAttributeMaxDynamicSharedMemorySize, FA_SMEM);

    dim3 g1((NTOK + 127) / 128, 24);                 // 43 x 24
    qkv_mma<<<g1, 256, QK_SMEM>>>(X, Wq, bq, Wk, bk, Wv, bv);

    dim3 g2((SEQ + 127) / 128, BATCH * NH);          // 11 x 64
    flash_mma<<<g2, 256, FA_SMEM>>>(out);
}